// round 8
// baseline (speedup 1.0000x reference)
#include <cuda_runtime.h>
#include <cuda_fp16.h>
#include <math.h>
#include <stdint.h>

#define BATCH 16
#define LSEQ  1024
#define HDIM  1024
#define NEGV  (-1000000000000.0f)
#define TRILV (1000000000000.0f)

// -------------------- scratch (allocation-free) --------------------
__device__ __half g_hbf[(size_t)BATCH * LSEQ * HDIM];   // hidden fp16 [M,K]
__device__ __half g_w1t[(size_t)2048 * 1024];           // W1^T fp16 [N,K]
__device__ __half g_q[(size_t)BATCH * LSEQ * HDIM];     // fp16 [B,L,H]
__device__ __half g_k[(size_t)BATCH * LSEQ * HDIM];
__device__ float  g_bias[BATCH * 4 * LSEQ];
__device__ float2 g_cs[(size_t)LSEQ * 512];             // (cos,sin) per (l, pair) 4MB

// -------------------- helpers (baseline PTX ISA only) --------------------
__device__ __forceinline__ uint32_t smem_u32(const void* p) {
    uint32_t a;
    asm("{ .reg .u64 t; cvta.to.shared.u64 t, %1; cvt.u32.u64 %0, t; }" : "=r"(a) : "l"(p));
    return a;
}
__device__ __forceinline__ void cp16(uint32_t dst, const void* src) {
    asm volatile("cp.async.cg.shared.global [%0], [%1], 16;" :: "r"(dst), "l"(src));
}
__device__ __forceinline__ void cp_commit() { asm volatile("cp.async.commit_group;" ::: "memory"); }
__device__ __forceinline__ void ldsm4(uint32_t* r, uint32_t addr) {
    asm volatile("ldmatrix.sync.aligned.m8n8.x4.shared.b16 {%0,%1,%2,%3}, [%4];"
                 : "=r"(r[0]), "=r"(r[1]), "=r"(r[2]), "=r"(r[3]) : "r"(addr));
}
__device__ __forceinline__ void mma16816(float* d, const uint32_t* a, uint32_t b0, uint32_t b1) {
    asm volatile("mma.sync.aligned.m16n8k16.row.col.f32.f16.f16.f32 "
                 "{%0,%1,%2,%3}, {%4,%5,%6,%7}, {%8,%9}, {%0,%1,%2,%3};"
                 : "+f"(d[0]), "+f"(d[1]), "+f"(d[2]), "+f"(d[3])
                 : "r"(a[0]), "r"(a[1]), "r"(a[2]), "r"(a[3]), "r"(b0), "r"(b1));
}

#define STAGE_BYTES 32768               // A 16KB + B 16KB per stage
#define DYN_SMEM    (1024 + 3 * STAGE_BYTES)   // align slack + 3 stages (epilogue reuses)

// -------------------- shared mainloop --------------------
// acc[mf][nf][e] = (A[128,1024] @ B[128,1024]^T) 128x128 tile, fp16 in fp32 acc.
// Warp grid 2(m) x 4(n); warp tile 64x32; fragments per mma.m16n8k16.
__device__ __forceinline__ void gemm_mainloop(const __half* __restrict__ Ab,
                                              const __half* __restrict__ Bb,
                                              uint32_t sb, float acc[4][4][4])
{
    const int tid = threadIdx.x, lane = tid & 31, wid = tid >> 5;
    const int wm = wid >> 2, wn = wid & 3;

    // cp.async loader: row = tid>>1 (0..127), 4x16B chunks
    const int lrow = tid >> 1;
    const int lc0 = (tid & 1) * 4;
    const __half* ap = Ab + (size_t)lrow * 1024 + lc0 * 8;
    const __half* bp = Bb + (size_t)lrow * 1024 + lc0 * 8;
    uint32_t soff[4];
    #pragma unroll
    for (int i = 0; i < 4; ++i) {
        uint32_t off = lrow * 128 + (lc0 + i) * 16;
        soff[i] = off ^ ((off >> 3) & 0x70);
    }
    uint32_t stA[3], stB[3];
    #pragma unroll
    for (int s = 0; s < 3; ++s) { stA[s] = sb + s * STAGE_BYTES; stB[s] = stA[s] + 16384; }

    // prologue: tiles 0,1
    #pragma unroll
    for (int t = 0; t < 2; ++t) {
        #pragma unroll
        for (int i = 0; i < 4; ++i) {
            cp16(stA[t] + soff[i], ap + t * 64 + i * 8);
            cp16(stB[t] + soff[i], bp + t * 64 + i * 8);
        }
        cp_commit();
    }

    const int lr = lane & 15, lhi = lane >> 4;
    const uint32_t xorterm = (uint32_t)(lr & 7) * 16;
    uint32_t aRow[4], bRow[2];
    #pragma unroll
    for (int mf = 0; mf < 4; ++mf) aRow[mf] = (uint32_t)(wm * 64 + mf * 16 + lr) * 128;
    #pragma unroll
    for (int nfp = 0; nfp < 2; ++nfp) bRow[nfp] = (uint32_t)(wn * 32 + nfp * 16 + lr) * 128;

    int scur = 0, spre = 2;     // rolling stage indices (no div/mod)
    #pragma unroll 1
    for (int kt = 0; kt < 16; ++kt) {
        if (kt == 15) asm volatile("cp.async.wait_group 0;" ::: "memory");
        else          asm volatile("cp.async.wait_group 1;" ::: "memory");
        __syncthreads();

        if (kt < 14) {
            const __half* app = ap + (kt + 2) * 64;
            const __half* bpp = bp + (kt + 2) * 64;
            const uint32_t pA = stA[spre], pB = stB[spre];
            #pragma unroll
            for (int i = 0; i < 4; ++i) {
                cp16(pA + soff[i], app + i * 8);
                cp16(pB + soff[i], bpp + i * 8);
            }
            cp_commit();
        }
        if (++spre == 3) spre = 0;

        const uint32_t sA = stA[scur], sB = stB[scur];
        if (++scur == 3) scur = 0;
        #pragma unroll
        for (int ks = 0; ks < 4; ++ks) {
            const uint32_t colbyte = ((uint32_t)(ks * 2 + lhi) * 16) ^ xorterm;
            uint32_t bfr[2][4];
            ldsm4(bfr[0], sB + bRow[0] + colbyte);
            ldsm4(bfr[1], sB + bRow[1] + colbyte);
            // 2-deep A-fragment pipeline: LDSM mf+1 overlaps MMAs of mf
            uint32_t afr[2][4];
            ldsm4(afr[0], sA + aRow[0] + colbyte);
            #pragma unroll
            for (int mf = 0; mf < 4; ++mf) {
                if (mf < 3) ldsm4(afr[(mf + 1) & 1], sA + aRow[mf + 1] + colbyte);
                const uint32_t* af = afr[mf & 1];
                #pragma unroll
                for (int nf = 0; nf < 4; ++nf)
                    mma16816(acc[mf][nf], af,
                             bfr[nf >> 1][nf & 1], bfr[nf >> 1][2 + (nf & 1)]);
            }
        }
    }
    __syncthreads();   // mainloop smem now reusable by epilogues
}

// -------------------- GEMM1: hidden @ W1 + b1, RoPE, scatter q/k --------------------
__global__ __launch_bounds__(256, 2) void gemm1_kernel(const float* __restrict__ b1v)
{
    extern __shared__ char smem_raw[];
    char* base = (char*)(((uintptr_t)smem_raw + 1023) & ~(uintptr_t)1023);
    const uint32_t sb = smem_u32(base);
    const int tid = threadIdx.x, lane = tid & 31, wid = tid >> 5;
    const int wm = wid >> 2, wn = wid & 3;
    const int m0 = blockIdx.y * 128, n0 = blockIdx.x * 128;

    float acc[4][4][4] = {};
    gemm_mainloop(g_hbf + (size_t)m0 * 1024, g_w1t + (size_t)n0 * 1024, sb, acc);

    // stage C tile to smem (raw acc; b1 added at read)
    float* Cb = (float*)base;      // [128][132]
    const int r0 = wm * 64 + (lane >> 2);
    const int c0l = wn * 32 + (lane & 3) * 2;
    #pragma unroll
    for (int mf = 0; mf < 4; ++mf)
        #pragma unroll
        for (int nf = 0; nf < 4; ++nf) {
            float* p = &Cb[(r0 + mf * 16) * 132 + c0l + nf * 8];
            *(float2*)p             = make_float2(acc[mf][nf][0], acc[mf][nf][1]);
            *(float2*)(p + 8 * 132) = make_float2(acc[mf][nf][2], acc[mf][nf][3]);
        }
    __syncthreads();

    // RoPE + scatter: one quad (4 cols) per thread-iter; trig from table
    #pragma unroll 1
    for (int it = 0; it < 16; ++it) {
        const int w = it * 256 + tid;
        const int r = w >> 5, quad = w & 31;
        float4 v = *(float4*)&Cb[r * 132 + quad * 4];
        const int cb = n0 + quad * 4;
        const int ir = cb >> 2;
        const int m = m0 + r;
        const int l = m & 1023;
        const float2 cs = g_cs[((size_t)l << 9) + ir];
        const float c = cs.x, s = cs.y;
        float q0 = v.x + b1v[cb + 0];
        float k0 = v.y + b1v[cb + 1];
        float q1 = v.z + b1v[cb + 2];
        float k1 = v.w + b1v[cb + 3];
        __half2 qh = __floats2half2_rn(q0 * c - q1 * s, q1 * c + q0 * s);
        __half2 kh = __floats2half2_rn(k0 * c - k1 * s, k1 * c + k0 * s);
        *(uint32_t*)&g_q[(size_t)m * 1024 + (cb >> 1)] = *reinterpret_cast<uint32_t*>(&qh);
        *(uint32_t*)&g_k[(size_t)m * 1024 + (cb >> 1)] = *reinterpret_cast<uint32_t*>(&kh);
    }
}

// -------------------- GEMM2: q @ k^T, scale + bias + masks + tril --------------------
__global__ __launch_bounds__(256, 2) void gemm2_kernel(const int* __restrict__ tt,
                                                       float* __restrict__ out)
{
    extern __shared__ char smem_raw[];
    __shared__ float s_tb[768];   // bE0[128] bE1[128] mc[128] | bO0[128] bO1[128] mr[128]
    char* base = (char*)(((uintptr_t)smem_raw + 1023) & ~(uintptr_t)1023);
    const uint32_t sb = smem_u32(base);
    const int tid = threadIdx.x, lane = tid & 31, wid = tid >> 5;
    const int wm = wid >> 2, wn = wid & 3;
    const int b = blockIdx.z, m0 = blockIdx.y * 128, n0 = blockIdx.x * 128;

    float acc[4][4][4] = {};
    gemm_mainloop(g_q + ((size_t)b << 20) + (size_t)m0 * 1024,
                  g_k + ((size_t)b << 20) + (size_t)n0 * 1024, sb, acc);

    if (tid < 128) {
        const int n = n0 + tid;
        s_tb[tid]       = g_bias[b * 4096 + n];
        s_tb[128 + tid] = g_bias[b * 4096 + 2048 + n];
        s_tb[256 + tid] = (float)tt[(b << 10) + n];
    } else {
        const int r = tid - 128, m = m0 + r;
        s_tb[384 + r] = g_bias[b * 4096 + 1024 + m];
        s_tb[512 + r] = g_bias[b * 4096 + 3072 + m];
        s_tb[640 + r] = (float)tt[(b << 10) + m];
    }
    __syncthreads();

    const float scale = 0.03125f;   // 1/sqrt(1024)
    #pragma unroll
    for (int mf = 0; mf < 4; ++mf) {
        #pragma unroll
        for (int h = 0; h < 2; ++h) {
            const int Rl = wm * 64 + mf * 16 + (lane >> 2) + h * 8;
            const int m = m0 + Rl;
            const float bo0 = s_tb[384 + Rl], bo1 = s_tb[512 + Rl], rm = s_tb[640 + Rl];
            float* o0 = out + ((size_t)(b * 2) * 1024 + m) * 1024 + n0;
            float* o1 = o0 + (size_t)1024 * 1024;
            #pragma unroll
            for (int nf = 0; nf < 4; ++nf) {
                const int Cl = wn * 32 + nf * 8 + (lane & 3) * 2;
                float2 r0v, r1v;
                #pragma unroll
                for (int e = 0; e < 2; ++e) {
                    const int nl = Cl + e;
                    const int n = n0 + nl;
                    const float v = acc[mf][nf][h * 2 + e] * scale;
                    const float keep = rm * s_tb[256 + nl];
                    float v0 = v + s_tb[nl]       + bo0;
                    float v1 = v + s_tb[128 + nl] + bo1;
                    v0 = (keep != 0.0f) ? v0 : NEGV;
                    v1 = (keep != 0.0f) ? v1 : NEGV;
                    if (m > n) { v0 -= TRILV; v1 -= TRILV; }
                    (&r0v.x)[e] = v0;
                    (&r1v.x)[e] = v1;
                }
                *(float2*)(o0 + Cl) = r0v;
                *(float2*)(o1 + Cl) = r1v;
            }
        }
    }
}

// -------------------- prep kernels --------------------
__global__ __launch_bounds__(256) void rope_cs_kernel()
{
    const int idx = blockIdx.x * 256 + threadIdx.x;   // l*512 + ir
    const int l = idx >> 9, ir = idx & 511;
    const float inv = expf(-(float)ir * (2.0f * 9.210340371976184f / 1024.0f));
    float s, c;
    sincosf((float)l * inv, &s, &c);
    g_cs[idx] = make_float2(c, s);
}

__global__ __launch_bounds__(256) void convert_hidden(const float* __restrict__ hidden)
{
    const size_t i = ((size_t)blockIdx.x * 256 + threadIdx.x) * 8;
    float4 a = *(const float4*)&hidden[i];
    float4 bq = *(const float4*)&hidden[i + 4];
    __half2 h0 = __floats2half2_rn(a.x, a.y);
    __half2 h1 = __floats2half2_rn(a.z, a.w);
    __half2 h2 = __floats2half2_rn(bq.x, bq.y);
    __half2 h3 = __floats2half2_rn(bq.z, bq.w);
    uint4 o;
    o.x = *reinterpret_cast<uint32_t*>(&h0);
    o.y = *reinterpret_cast<uint32_t*>(&h1);
    o.z = *reinterpret_cast<uint32_t*>(&h2);
    o.w = *reinterpret_cast<uint32_t*>(&h3);
    *(uint4*)&g_hbf[i] = o;
}

__global__ __launch_bounds__(256) void transpose_w1(const float* __restrict__ W1)
{
    __shared__ float tile[32][33];
    const int tx = threadIdx.x & 31, ty = threadIdx.x >> 5;   // 32x8
    const int nb = blockIdx.x * 32, kb = blockIdx.y * 32;
    #pragma unroll
    for (int i = 0; i < 4; ++i)
        tile[ty + i * 8][tx] = W1[(size_t)(kb + ty + i * 8) * 2048 + nb + tx];
    __syncthreads();
    #pragma unroll
    for (int i = 0; i < 4; ++i)
        g_w1t[(size_t)(nb + ty + i * 8) * 1024 + kb + tx] = __float2half_rn(tile[tx][ty + i * 8]);
}

__global__ __launch_bounds__(256) void bias2_kernel(const float* __restrict__ hidden,
                                                    const float* __restrict__ W2,
                                                    const float* __restrict__ b2)
{
    const int wid = threadIdx.x >> 5, lane = threadIdx.x & 31;
    const int rowm = blockIdx.x * 8 + wid;                    // 0..16383
    const float* h = hidden + (size_t)rowm * 1024;
    float a0 = 0.f, a1 = 0.f, a2 = 0.f, a3 = 0.f;
    #pragma unroll 8
    for (int i = 0; i < 32; ++i) {
        const int k = i * 32 + lane;
        const float hv = h[k];
        float4 w = *(const float4*)&W2[k * 4];
        a0 = fmaf(hv, w.x, a0);
        a1 = fmaf(hv, w.y, a1);
        a2 = fmaf(hv, w.z, a2);
        a3 = fmaf(hv, w.w, a3);
    }
    #pragma unroll
    for (int off = 16; off > 0; off >>= 1) {
        a0 += __shfl_xor_sync(0xFFFFFFFF, a0, off);
        a1 += __shfl_xor_sync(0xFFFFFFFF, a1, off);
        a2 += __shfl_xor_sync(0xFFFFFFFF, a2, off);
        a3 += __shfl_xor_sync(0xFFFFFFFF, a3, off);
    }
    if (lane == 0) {
        const int bb = rowm >> 10, l = rowm & 1023;
        float* bp = g_bias + (size_t)bb * 4096 + l;
        bp[0]    = (a0 + b2[0]) * 0.5f;
        bp[1024] = (a1 + b2[1]) * 0.5f;
        bp[2048] = (a2 + b2[2]) * 0.5f;
        bp[3072] = (a3 + b2[3]) * 0.5f;
    }
}

// -------------------- launch --------------------
extern "C" void kernel_launch(void* const* d_in, const int* in_sizes, int n_in,
                              void* d_out, int out_size)
{
    const float* hidden = (const float*)d_in[0];
    const int*   tt     = (const int*)d_in[1];
    const float* W1     = (const float*)d_in[2];
    const float* b1     = (const float*)d_in[3];
    const float* W2     = (const float*)d_in[4];
    const float* b2     = (const float*)d_in[5];
    float* out = (float*)d_out;

    cudaFuncSetAttribute(gemm1_kernel, cudaFuncAttributeMaxDynamicSharedMemorySize, DYN_SMEM);
    cudaFuncSetAttribute(gemm2_kernel, cudaFuncAttributeMaxDynamicSharedMemorySize, DYN_SMEM);

    rope_cs_kernel<<<2048, 256>>>();
    convert_hidden<<<8192, 256>>>(hidden);
    transpose_w1<<<dim3(64, 32), dim3(256)>>>(W1);
    bias2_kernel<<<2048, 256>>>(hidden, W2, b2);

    dim3 g1(16, 128);                 // N/128 x M/128
    gemm1_kernel<<<g1, 256, DYN_SMEM>>>(b1);

    dim3 g2(8, 8, BATCH);             // N/128 x M/128 x B
    gemm2_kernel<<<g2, 256, DYN_SMEM>>>(tt, out);
}

// round 9
// speedup vs baseline: 1.0921x; 1.0921x over previous
#include <cuda_runtime.h>
#include <cuda_fp16.h>
#include <math.h>
#include <stdint.h>

#define BATCH 16
#define LSEQ  1024
#define HDIM  1024
#define NEGV  (-1000000000000.0f)
#define TRILV (1000000000000.0f)

// -------------------- scratch (allocation-free) --------------------
__device__ __half g_hbf[(size_t)BATCH * LSEQ * HDIM];   // hidden fp16 [M,K]
__device__ __half g_w1t[(size_t)2048 * 1024];           // W1^T fp16 [N,K]
__device__ __half g_q[(size_t)BATCH * LSEQ * HDIM];     // fp16 [B,L,H]
__device__ __half g_k[(size_t)BATCH * LSEQ * HDIM];
__device__ float  g_bias[BATCH * 4 * LSEQ];

// -------------------- helpers (baseline PTX ISA only) --------------------
__device__ __forceinline__ uint32_t smem_u32(const void* p) {
    uint32_t a;
    asm("{ .reg .u64 t; cvta.to.shared.u64 t, %1; cvt.u32.u64 %0, t; }" : "=r"(a) : "l"(p));
    return a;
}
__device__ __forceinline__ void cp16(uint32_t dst, const void* src) {
    asm volatile("cp.async.cg.shared.global [%0], [%1], 16;" :: "r"(dst), "l"(src));
}
__device__ __forceinline__ void cp_commit() { asm volatile("cp.async.commit_group;" ::: "memory"); }
__device__ __forceinline__ void ldsm4(uint32_t* r, uint32_t addr) {
    asm volatile("ldmatrix.sync.aligned.m8n8.x4.shared.b16 {%0,%1,%2,%3}, [%4];"
                 : "=r"(r[0]), "=r"(r[1]), "=r"(r[2]), "=r"(r[3]) : "r"(addr));
}
__device__ __forceinline__ void mma16816(float* d, const uint32_t* a, uint32_t b0, uint32_t b1) {
    asm volatile("mma.sync.aligned.m16n8k16.row.col.f32.f16.f16.f32 "
                 "{%0,%1,%2,%3}, {%4,%5,%6,%7}, {%8,%9}, {%0,%1,%2,%3};"
                 : "+f"(d[0]), "+f"(d[1]), "+f"(d[2]), "+f"(d[3])
                 : "r"(a[0]), "r"(a[1]), "r"(a[2]), "r"(a[3]), "r"(b0), "r"(b1));
}

#define STAGE_BYTES 32768               // A 16KB + B 16KB per stage
#define DYN_SMEM    (1024 + 3 * STAGE_BYTES)   // align slack + 3 stages (epilogue reuses)

// -------------------- shared mainloop (R4 configuration — measured best) -----
__device__ __forceinline__ void gemm_mainloop(const __half* __restrict__ Ab,
                                              const __half* __restrict__ Bb,
                                              uint32_t sb, float acc[4][4][4])
{
    const int tid = threadIdx.x, lane = tid & 31, wid = tid >> 5;
    const int wm = wid >> 2, wn = wid & 3;

    const int lrow = tid >> 1;
    const int lc0 = (tid & 1) * 4;
    const __half* ap = Ab + (size_t)lrow * 1024 + lc0 * 8;
    const __half* bp = Bb + (size_t)lrow * 1024 + lc0 * 8;
    uint32_t soff[4];
    #pragma unroll
    for (int i = 0; i < 4; ++i) {
        uint32_t off = lrow * 128 + (lc0 + i) * 16;
        soff[i] = off ^ ((off >> 3) & 0x70);
    }
    uint32_t stA[3], stB[3];
    #pragma unroll
    for (int s = 0; s < 3; ++s) { stA[s] = sb + s * STAGE_BYTES; stB[s] = stA[s] + 16384; }

    #pragma unroll
    for (int t = 0; t < 2; ++t) {
        #pragma unroll
        for (int i = 0; i < 4; ++i) {
            cp16(stA[t] + soff[i], ap + t * 64 + i * 8);
            cp16(stB[t] + soff[i], bp + t * 64 + i * 8);
        }
        cp_commit();
    }

    const int lr = lane & 15, lhi = lane >> 4;
    const uint32_t xorterm = (uint32_t)(lr & 7) * 16;
    uint32_t aRow[4], bRow[2];
    #pragma unroll
    for (int mf = 0; mf < 4; ++mf) aRow[mf] = (uint32_t)(wm * 64 + mf * 16 + lr) * 128;
    #pragma unroll
    for (int nfp = 0; nfp < 2; ++nfp) bRow[nfp] = (uint32_t)(wn * 32 + nfp * 16 + lr) * 128;

    #pragma unroll 1
    for (int kt = 0; kt < 16; ++kt) {
        if (kt == 15) asm volatile("cp.async.wait_group 0;" ::: "memory");
        else          asm volatile("cp.async.wait_group 1;" ::: "memory");
        __syncthreads();

        if (kt < 14) {
            const int t = kt + 2;
            const int sl = t - (t / 3) * 3;
            #pragma unroll
            for (int i = 0; i < 4; ++i) {
                cp16(stA[sl] + soff[i], ap + t * 64 + i * 8);
                cp16(stB[sl] + soff[i], bp + t * 64 + i * 8);
            }
            cp_commit();
        }

        const int s = kt - (kt / 3) * 3;
        const uint32_t sA = stA[s], sB = stB[s];
        #pragma unroll
        for (int ks = 0; ks < 4; ++ks) {
            const uint32_t colbyte = ((uint32_t)(ks * 2 + lhi) * 16) ^ xorterm;
            uint32_t bfr[2][4];
            #pragma unroll
            for (int nfp = 0; nfp < 2; ++nfp) ldsm4(bfr[nfp], sB + bRow[nfp] + colbyte);
            #pragma unroll
            for (int mf = 0; mf < 4; ++mf) {
                uint32_t afr[4];
                ldsm4(afr, sA + aRow[mf] + colbyte);
                #pragma unroll
                for (int nf = 0; nf < 4; ++nf)
                    mma16816(acc[mf][nf], afr,
                             bfr[nf >> 1][nf & 1], bfr[nf >> 1][2 + (nf & 1)]);
            }
        }
    }
    __syncthreads();   // mainloop smem now reusable by epilogues
}

// -------------------- GEMM1: hidden @ W1 + b1, RoPE, scatter q/k --------------------
__global__ __launch_bounds__(256, 2) void gemm1_kernel(const float* __restrict__ b1v)
{
    extern __shared__ char smem_raw[];
    char* base = (char*)(((uintptr_t)smem_raw + 1023) & ~(uintptr_t)1023);
    const uint32_t sb = smem_u32(base);
    const int tid = threadIdx.x, lane = tid & 31, wid = tid >> 5;
    const int wm = wid >> 2, wn = wid & 3;
    const int m0 = blockIdx.y * 128, n0 = blockIdx.x * 128;

    float acc[4][4][4] = {};
    gemm_mainloop(g_hbf + (size_t)m0 * 1024, g_w1t + (size_t)n0 * 1024, sb, acc);

    float* Cb = (float*)base;      // [128][132]
    const int r0 = wm * 64 + (lane >> 2);
    const int c0l = wn * 32 + (lane & 3) * 2;
    #pragma unroll
    for (int mf = 0; mf < 4; ++mf)
        #pragma unroll
        for (int nf = 0; nf < 4; ++nf) {
            float* p = &Cb[(r0 + mf * 16) * 132 + c0l + nf * 8];
            *(float2*)p             = make_float2(acc[mf][nf][0], acc[mf][nf][1]);
            *(float2*)(p + 8 * 132) = make_float2(acc[mf][nf][2], acc[mf][nf][3]);
        }
    __syncthreads();

    #pragma unroll 1
    for (int it = 0; it < 16; ++it) {
        const int w = it * 256 + tid;
        const int r = w >> 5, quad = w & 31;
        float4 v = *(float4*)&Cb[r * 132 + quad * 4];
        const int cb = n0 + quad * 4;
        const int ir = cb >> 2;
        const int m = m0 + r;
        const int l = m & 1023;
        const float inv = expf(-(float)ir * (2.0f * 9.210340371976184f / 1024.0f));
        float s, c;
        sincosf((float)l * inv, &s, &c);
        float q0 = v.x + b1v[cb + 0];
        float k0 = v.y + b1v[cb + 1];
        float q1 = v.z + b1v[cb + 2];
        float k1 = v.w + b1v[cb + 3];
        __half2 qh = __floats2half2_rn(q0 * c - q1 * s, q1 * c + q0 * s);
        __half2 kh = __floats2half2_rn(k0 * c - k1 * s, k1 * c + k0 * s);
        *(uint32_t*)&g_q[(size_t)m * 1024 + (cb >> 1)] = *reinterpret_cast<uint32_t*>(&qh);
        *(uint32_t*)&g_k[(size_t)m * 1024 + (cb >> 1)] = *reinterpret_cast<uint32_t*>(&kh);
    }
}

// -------------------- GEMM2: q @ k^T, scale + bias + masks + tril --------------------
// Blocks fully below the diagonal need NO GEMM: after `- tril*1e12` the fp32
// rounding (ulp(1e12)=65536 >> |qk+bias|) makes the result exactly
// -float(1e12) (both masks 1) or -2*float(1e12) (any mask 0) — identical to
// the fp32 reference. Fill them directly.
__global__ __launch_bounds__(256, 2) void gemm2_kernel(const int* __restrict__ tt,
                                                       float* __restrict__ out)
{
    extern __shared__ char smem_raw[];
    __shared__ float s_tb[768];   // bE0[128] bE1[128] mc[128] | bO0[128] bO1[128] mr[128]
    char* base = (char*)(((uintptr_t)smem_raw + 1023) & ~(uintptr_t)1023);
    const uint32_t sb = smem_u32(base);
    const int tid = threadIdx.x, lane = tid & 31, wid = tid >> 5;
    const int wm = wid >> 2, wn = wid & 3;
    const int b = blockIdx.z, m0 = blockIdx.y * 128, n0 = blockIdx.x * 128;

    if (m0 >= n0 + 128) {
        // ---- constant-fill path (strict lower triangle) ----
        __shared__ int s_m[256];            // mr[128] | mc[128]
        if (tid < 128) s_m[tid] = tt[(b << 10) + m0 + tid];
        else           s_m[128 + (tid - 128)] = tt[(b << 10) + n0 + (tid - 128)];
        __syncthreads();
        const float F1 = -1e12f, F2 = -2e12f;
        const int r = tid >> 1, hh = tid & 1;     // row 0..127, 64-col half
        const int mr = s_m[r];
        float* o0 = out + ((size_t)(b * 2) * 1024 + m0 + r) * 1024 + n0 + hh * 64;
        float* o1 = o0 + (size_t)1024 * 1024;
        #pragma unroll
        for (int j = 0; j < 16; ++j) {
            float4 v;
            #pragma unroll
            for (int e = 0; e < 4; ++e) {
                const int mc = s_m[128 + hh * 64 + j * 4 + e];
                (&v.x)[e] = (mr & mc) ? F1 : F2;
            }
            *(float4*)(o0 + j * 4) = v;
            *(float4*)(o1 + j * 4) = v;
        }
        return;
    }

    float acc[4][4][4] = {};
    gemm_mainloop(g_q + ((size_t)b << 20) + (size_t)m0 * 1024,
                  g_k + ((size_t)b << 20) + (size_t)n0 * 1024, sb, acc);

    if (tid < 128) {
        const int n = n0 + tid;
        s_tb[tid]       = g_bias[b * 4096 + n];
        s_tb[128 + tid] = g_bias[b * 4096 + 2048 + n];
        s_tb[256 + tid] = (float)tt[(b << 10) + n];
    } else {
        const int r = tid - 128, m = m0 + r;
        s_tb[384 + r] = g_bias[b * 4096 + 1024 + m];
        s_tb[512 + r] = g_bias[b * 4096 + 3072 + m];
        s_tb[640 + r] = (float)tt[(b << 10) + m];
    }
    __syncthreads();

    const float scale = 0.03125f;   // 1/sqrt(1024)
    #pragma unroll
    for (int mf = 0; mf < 4; ++mf) {
        #pragma unroll
        for (int h = 0; h < 2; ++h) {
            const int Rl = wm * 64 + mf * 16 + (lane >> 2) + h * 8;
            const int m = m0 + Rl;
            const float bo0 = s_tb[384 + Rl], bo1 = s_tb[512 + Rl], rm = s_tb[640 + Rl];
            float* o0 = out + ((size_t)(b * 2) * 1024 + m) * 1024 + n0;
            float* o1 = o0 + (size_t)1024 * 1024;
            #pragma unroll
            for (int nf = 0; nf < 4; ++nf) {
                const int Cl = wn * 32 + nf * 8 + (lane & 3) * 2;
                float2 r0v, r1v;
                #pragma unroll
                for (int e = 0; e < 2; ++e) {
                    const int nl = Cl + e;
                    const int n = n0 + nl;
                    const float v = acc[mf][nf][h * 2 + e] * scale;
                    const float keep = rm * s_tb[256 + nl];
                    float v0 = v + s_tb[nl]       + bo0;
                    float v1 = v + s_tb[128 + nl] + bo1;
                    v0 = (keep != 0.0f) ? v0 : NEGV;
                    v1 = (keep != 0.0f) ? v1 : NEGV;
                    if (m > n) { v0 -= TRILV; v1 -= TRILV; }
                    (&r0v.x)[e] = v0;
                    (&r1v.x)[e] = v1;
                }
                *(float2*)(o0 + Cl) = r0v;
                *(float2*)(o1 + Cl) = r1v;
            }
        }
    }
}

// -------------------- prep: fused hidden->fp16 convert + bias GEMV --------------------
__global__ __launch_bounds__(256) void prep_hidden(const float* __restrict__ hidden,
                                                   const float* __restrict__ W2,
                                                   const float* __restrict__ b2)
{
    const int wid = threadIdx.x >> 5, lane = threadIdx.x & 31;
    const int row = blockIdx.x * 8 + wid;                     // 0..16383
    const float* h = hidden + (size_t)row * 1024;
    __half* o = g_hbf + (size_t)row * 1024;
    float a0 = 0.f, a1 = 0.f, a2 = 0.f, a3 = 0.f;
    #pragma unroll
    for (int i = 0; i < 8; ++i) {
        const int c4 = i * 32 + lane;                          // float4 index in row
        float4 v = *(const float4*)&h[c4 * 4];
        __half2 h0 = __floats2half2_rn(v.x, v.y);
        __half2 h1 = __floats2half2_rn(v.z, v.w);
        uint2 st;
        st.x = *reinterpret_cast<uint32_t*>(&h0);
        st.y = *reinterpret_cast<uint32_t*>(&h1);
        *(uint2*)&o[c4 * 4] = st;
        const int k = c4 * 4;
        float4 w0 = *(const float4*)&W2[(k + 0) * 4];
        float4 w1 = *(const float4*)&W2[(k + 1) * 4];
        float4 w2 = *(const float4*)&W2[(k + 2) * 4];
        float4 w3 = *(const float4*)&W2[(k + 3) * 4];
        a0 += v.x * w0.x + v.y * w1.x + v.z * w2.x + v.w * w3.x;
        a1 += v.x * w0.y + v.y * w1.y + v.z * w2.y + v.w * w3.y;
        a2 += v.x * w0.z + v.y * w1.z + v.z * w2.z + v.w * w3.z;
        a3 += v.x * w0.w + v.y * w1.w + v.z * w2.w + v.w * w3.w;
    }
    #pragma unroll
    for (int off = 16; off > 0; off >>= 1) {
        a0 += __shfl_xor_sync(0xFFFFFFFF, a0, off);
        a1 += __shfl_xor_sync(0xFFFFFFFF, a1, off);
        a2 += __shfl_xor_sync(0xFFFFFFFF, a2, off);
        a3 += __shfl_xor_sync(0xFFFFFFFF, a3, off);
    }
    if (lane == 0) {
        const int bb = row >> 10, l = row & 1023;
        float* bp = g_bias + (size_t)bb * 4096 + l;
        bp[0]    = (a0 + b2[0]) * 0.5f;
        bp[1024] = (a1 + b2[1]) * 0.5f;
        bp[2048] = (a2 + b2[2]) * 0.5f;
        bp[3072] = (a3 + b2[3]) * 0.5f;
    }
}

__global__ __launch_bounds__(256) void transpose_w1(const float* __restrict__ W1)
{
    __shared__ float tile[32][33];
    const int tx = threadIdx.x & 31, ty = threadIdx.x >> 5;   // 32x8
    const int nb = blockIdx.x * 32, kb = blockIdx.y * 32;
    #pragma unroll
    for (int i = 0; i < 4; ++i)
        tile[ty + i * 8][tx] = W1[(size_t)(kb + ty + i * 8) * 2048 + nb + tx];
    __syncthreads();
    #pragma unroll
    for (int i = 0; i < 4; ++i)
        g_w1t[(size_t)(nb + ty + i * 8) * 1024 + kb + tx] = __float2half_rn(tile[tx][ty + i * 8]);
}

// -------------------- launch --------------------
extern "C" void kernel_launch(void* const* d_in, const int* in_sizes, int n_in,
                              void* d_out, int out_size)
{
    const float* hidden = (const float*)d_in[0];
    const int*   tt     = (const int*)d_in[1];
    const float* W1     = (const float*)d_in[2];
    const float* b1     = (const float*)d_in[3];
    const float* W2     = (const float*)d_in[4];
    const float* b2     = (const float*)d_in[5];
    float* out = (float*)d_out;

    cudaFuncSetAttribute(gemm1_kernel, cudaFuncAttributeMaxDynamicSharedMemorySize, DYN_SMEM);
    cudaFuncSetAttribute(gemm2_kernel, cudaFuncAttributeMaxDynamicSharedMemorySize, DYN_SMEM);

    prep_hidden<<<2048, 256>>>(hidden, W2, b2);
    transpose_w1<<<dim3(64, 32), dim3(256)>>>(W1);

    dim3 g1(16, 128);                 // N/128 x M/128
    gemm1_kernel<<<g1, 256, DYN_SMEM>>>(b1);

    dim3 g2(8, 8, BATCH);             // N/128 x M/128 x B
    gemm2_kernel<<<g2, 256, DYN_SMEM>>>(tt, out);
}

// round 10
// speedup vs baseline: 1.6433x; 1.5047x over previous
#include <cuda_runtime.h>
#include <cuda_fp16.h>
#include <math.h>
#include <stdint.h>

#define BATCH 16
#define LSEQ  1024
#define HDIM  1024

// -------------------- scratch (allocation-free) --------------------
__device__ __half g_hbf[(size_t)BATCH * LSEQ * HDIM];   // hidden fp16 [B*L, H]
__device__ __half g_w1t[(size_t)2048 * 1024];           // W1^T fp16 [N, K]
__device__ __half g_qc[(size_t)BATCH * LSEQ * HDIM];    // compacted q' fp16
__device__ __half g_kc[(size_t)BATCH * LSEQ * HDIM];    // compacted k' fp16
__device__ float  g_qk[(size_t)BATCH * LSEQ * LSEQ];    // compacted raw qk (64MB)
__device__ float  g_bias[BATCH * 4 * LSEQ];
__device__ int    g_idx[BATCH * LSEQ];                  // compact -> orig
__device__ int    g_rank[BATCH * LSEQ];                 // orig -> compact
__device__ int    g_cnt[BATCH];

// -------------------- helpers (baseline PTX ISA only) --------------------
__device__ __forceinline__ uint32_t smem_u32(const void* p) {
    uint32_t a;
    asm("{ .reg .u64 t; cvta.to.shared.u64 t, %1; cvt.u32.u64 %0, t; }" : "=r"(a) : "l"(p));
    return a;
}
__device__ __forceinline__ void cp16(uint32_t dst, const void* src) {
    asm volatile("cp.async.cg.shared.global [%0], [%1], 16;" :: "r"(dst), "l"(src));
}
__device__ __forceinline__ void cp_commit() { asm volatile("cp.async.commit_group;" ::: "memory"); }
__device__ __forceinline__ void ldsm4(uint32_t* r, uint32_t addr) {
    asm volatile("ldmatrix.sync.aligned.m8n8.x4.shared.b16 {%0,%1,%2,%3}, [%4];"
                 : "=r"(r[0]), "=r"(r[1]), "=r"(r[2]), "=r"(r[3]) : "r"(addr));
}
__device__ __forceinline__ void mma16816(float* d, const uint32_t* a, uint32_t b0, uint32_t b1) {
    asm volatile("mma.sync.aligned.m16n8k16.row.col.f32.f16.f16.f32 "
                 "{%0,%1,%2,%3}, {%4,%5,%6,%7}, {%8,%9}, {%0,%1,%2,%3};"
                 : "+f"(d[0]), "+f"(d[1]), "+f"(d[2]), "+f"(d[3])
                 : "r"(a[0]), "r"(a[1]), "r"(a[2]), "r"(a[3]), "r"(b0), "r"(b1));
}

#define STAGE_BYTES 32768               // A 16KB + B 16KB per stage
#define DYN_SMEM    (1024 + 3 * STAGE_BYTES)

// -------------------- shared mainloop (R4 config — measured best) -----------
// ap/bp: per-thread source pointers for row (tid>>1), 64B chunk (tid&1).
__device__ __forceinline__ void gemm_mainloop(const __half* __restrict__ ap,
                                              const __half* __restrict__ bp,
                                              uint32_t sb, float acc[4][4][4])
{
    const int tid = threadIdx.x, lane = tid & 31, wid = tid >> 5;
    const int wm = wid >> 2, wn = wid & 3;

    const int lrow = tid >> 1;
    const int lc0 = (tid & 1) * 4;
    uint32_t soff[4];
    #pragma unroll
    for (int i = 0; i < 4; ++i) {
        uint32_t off = lrow * 128 + (lc0 + i) * 16;
        soff[i] = off ^ ((off >> 3) & 0x70);
    }
    uint32_t stA[3], stB[3];
    #pragma unroll
    for (int s = 0; s < 3; ++s) { stA[s] = sb + s * STAGE_BYTES; stB[s] = stA[s] + 16384; }

    #pragma unroll
    for (int t = 0; t < 2; ++t) {
        #pragma unroll
        for (int i = 0; i < 4; ++i) {
            cp16(stA[t] + soff[i], ap + t * 64 + i * 8);
            cp16(stB[t] + soff[i], bp + t * 64 + i * 8);
        }
        cp_commit();
    }

    const int lr = lane & 15, lhi = lane >> 4;
    const uint32_t xorterm = (uint32_t)(lr & 7) * 16;
    uint32_t aRow[4], bRow[2];
    #pragma unroll
    for (int mf = 0; mf < 4; ++mf) aRow[mf] = (uint32_t)(wm * 64 + mf * 16 + lr) * 128;
    #pragma unroll
    for (int nfp = 0; nfp < 2; ++nfp) bRow[nfp] = (uint32_t)(wn * 32 + nfp * 16 + lr) * 128;

    #pragma unroll 1
    for (int kt = 0; kt < 16; ++kt) {
        if (kt == 15) asm volatile("cp.async.wait_group 0;" ::: "memory");
        else          asm volatile("cp.async.wait_group 1;" ::: "memory");
        __syncthreads();

        if (kt < 14) {
            const int t = kt + 2;
            const int sl = t - (t / 3) * 3;
            #pragma unroll
            for (int i = 0; i < 4; ++i) {
                cp16(stA[sl] + soff[i], ap + t * 64 + i * 8);
                cp16(stB[sl] + soff[i], bp + t * 64 + i * 8);
            }
            cp_commit();
        }

        const int s = kt - (kt / 3) * 3;
        const uint32_t sA = stA[s], sB = stB[s];
        #pragma unroll
        for (int ks = 0; ks < 4; ++ks) {
            const uint32_t colbyte = ((uint32_t)(ks * 2 + lhi) * 16) ^ xorterm;
            uint32_t bfr[2][4];
            #pragma unroll
            for (int nfp = 0; nfp < 2; ++nfp) ldsm4(bfr[nfp], sB + bRow[nfp] + colbyte);
            #pragma unroll
            for (int mf = 0; mf < 4; ++mf) {
                uint32_t afr[4];
                ldsm4(afr, sA + aRow[mf] + colbyte);
                #pragma unroll
                for (int nf = 0; nf < 4; ++nf)
                    mma16816(acc[mf][nf], afr,
                             bfr[nf >> 1][nf & 1], bfr[nf >> 1][2 + (nf & 1)]);
            }
        }
    }
    __syncthreads();   // mainloop smem reusable by epilogues
}

// -------------------- compaction: per-batch prefix sum over tt --------------
__global__ __launch_bounds__(1024) void compact_kernel(const int* __restrict__ tt)
{
    __shared__ int sc[2][1024];
    const int b = blockIdx.x, j = threadIdx.x;
    const int v = tt[(b << 10) + j];
    sc[0][j] = v;
    __syncthreads();
    int cur = 0;
    #pragma unroll
    for (int d = 1; d < 1024; d <<= 1) {
        int x = sc[cur][j];
        if (j >= d) x += sc[cur][j - d];
        sc[cur ^ 1][j] = x;
        __syncthreads();
        cur ^= 1;
    }
    const int incl = sc[cur][j];
    const int rank = incl - v;
    const int cnt = sc[cur][1023];
    g_rank[(b << 10) + j] = rank;
    if (v) g_idx[(b << 10) + rank] = j;
    if (j >= cnt) g_idx[(b << 10) + j] = 0;
    if (j == 0) g_cnt[b] = cnt;
}

// -------------------- GEMM1c: compacted rows of hidden @ W1 + b1, RoPE ------
__global__ __launch_bounds__(256, 2) void gemm1_kernel(const float* __restrict__ b1v)
{
    extern __shared__ char smem_raw[];
    char* base = (char*)(((uintptr_t)smem_raw + 1023) & ~(uintptr_t)1023);
    const uint32_t sb = smem_u32(base);
    const int tid = threadIdx.x, lane = tid & 31, wid = tid >> 5;
    const int wm = wid >> 2, wn = wid & 3;
    const int b = blockIdx.z;
    const int m0 = blockIdx.y * 128, n0 = blockIdx.x * 128;
    if (m0 >= g_cnt[b]) return;

    const int lrow = tid >> 1, lc0 = (tid & 1) * 4;
    const int lorig = g_idx[(b << 10) + m0 + lrow];
    const __half* ap = g_hbf + ((size_t)(b << 10) + lorig) * 1024 + lc0 * 8;
    const __half* bp = g_w1t + (size_t)(n0 + lrow) * 1024 + lc0 * 8;

    float acc[4][4][4] = {};
    gemm_mainloop(ap, bp, sb, acc);

    float* Cb = (float*)base;      // [128][132]
    const int r0 = wm * 64 + (lane >> 2);
    const int c0l = wn * 32 + (lane & 3) * 2;
    #pragma unroll
    for (int mf = 0; mf < 4; ++mf)
        #pragma unroll
        for (int nf = 0; nf < 4; ++nf) {
            float* p = &Cb[(r0 + mf * 16) * 132 + c0l + nf * 8];
            *(float2*)p             = make_float2(acc[mf][nf][0], acc[mf][nf][1]);
            *(float2*)(p + 8 * 132) = make_float2(acc[mf][nf][2], acc[mf][nf][3]);
        }
    __syncthreads();

    #pragma unroll 1
    for (int it = 0; it < 16; ++it) {
        const int w = it * 256 + tid;
        const int r = w >> 5, quad = w & 31;
        float4 v = *(float4*)&Cb[r * 132 + quad * 4];
        const int cb = n0 + quad * 4;
        const int ir = cb >> 2;
        const int j = m0 + r;                       // compact row
        const int l = g_idx[(b << 10) + j];         // original position
        const float inv = expf(-(float)ir * (2.0f * 9.210340371976184f / 1024.0f));
        float s, c;
        sincosf((float)l * inv, &s, &c);
        float q0 = v.x + b1v[cb + 0];
        float k0 = v.y + b1v[cb + 1];
        float q1 = v.z + b1v[cb + 2];
        float k1 = v.w + b1v[cb + 3];
        __half2 qh = __floats2half2_rn(q0 * c - q1 * s, q1 * c + q0 * s);
        __half2 kh = __floats2half2_rn(k0 * c - k1 * s, k1 * c + k0 * s);
        const size_t dst = ((size_t)(b << 10) + j) * 1024 + (cb >> 1);
        *(uint32_t*)&g_qc[dst] = *reinterpret_cast<uint32_t*>(&qh);
        *(uint32_t*)&g_kc[dst] = *reinterpret_cast<uint32_t*>(&kh);
    }
}

// -------------------- GEMM2c: compacted q' @ k'^T -> raw qk scratch ---------
__global__ __launch_bounds__(256, 2) void gemm2_kernel()
{
    extern __shared__ char smem_raw[];
    char* base = (char*)(((uintptr_t)smem_raw + 1023) & ~(uintptr_t)1023);
    const uint32_t sb = smem_u32(base);
    const int tid = threadIdx.x, lane = tid & 31, wid = tid >> 5;
    const int wm = wid >> 2, wn = wid & 3;
    const int b = blockIdx.z, m0 = blockIdx.y * 128, n0 = blockIdx.x * 128;
    const int c = g_cnt[b];
    if (m0 >= c || n0 >= c || m0 > n0 + 127) return;   // lower-tri / empty skip

    const int lrow = tid >> 1, lc0 = (tid & 1) * 4;
    const __half* ap = g_qc + ((size_t)(b << 10) + m0 + lrow) * 1024 + lc0 * 8;
    const __half* bp = g_kc + ((size_t)(b << 10) + n0 + lrow) * 1024 + lc0 * 8;

    float acc[4][4][4] = {};
    gemm_mainloop(ap, bp, sb, acc);

    #pragma unroll
    for (int mf = 0; mf < 4; ++mf)
        #pragma unroll
        for (int h = 0; h < 2; ++h) {
            const int Rl = wm * 64 + mf * 16 + (lane >> 2) + h * 8;
            float* orow = g_qk + ((size_t)b << 20) + (size_t)(m0 + Rl) * 1024 + n0;
            #pragma unroll
            for (int nf = 0; nf < 4; ++nf) {
                const int Cl = wn * 32 + nf * 8 + (lane & 3) * 2;
                *(float2*)(orow + Cl) =
                    make_float2(acc[mf][nf][h * 2], acc[mf][nf][h * 2 + 1]);
            }
        }
}

// -------------------- scatter/fill: produce full output ---------------------
// case table (bit-exact vs fp32 reference, since |qk/32+biases| << ulp(1e12)):
//   unmasked & m<=n : qk/32 + bE + bO
//   unmasked & m>n  : -1e12f
//   masked   & m<=n : -1e12f
//   masked   & m>n  : -2e12f
__global__ __launch_bounds__(256) void scatter_kernel(const int* __restrict__ tt,
                                                      float* __restrict__ out)
{
    const int b = blockIdx.y, m = blockIdx.x, tid = threadIdx.x;
    const int mr = tt[(b << 10) + m];
    const int rank_m = g_rank[(b << 10) + m];
    const float bo0 = g_bias[b * 4096 + 1024 + m];
    const float bo1 = g_bias[b * 4096 + 3072 + m];
    const float* qrow = g_qk + ((size_t)b << 20) + (size_t)rank_m * 1024;
    float* o0 = out + ((size_t)(b * 2) << 20) + (size_t)m * 1024;
    float* o1 = o0 + (size_t)(1 << 20);

    const int n4 = tid * 4;
    const int4  mc4 = *(const int4*)&tt[(b << 10) + n4];
    const int4  rk4 = *(const int4*)&g_rank[(b << 10) + n4];
    const float4 be0 = *(const float4*)&g_bias[b * 4096 + n4];
    const float4 be1 = *(const float4*)&g_bias[b * 4096 + 2048 + n4];

    float4 v0, v1;
    const int mcs[4] = {mc4.x, mc4.y, mc4.z, mc4.w};
    const int rks[4] = {rk4.x, rk4.y, rk4.z, rk4.w};
    #pragma unroll
    for (int e = 0; e < 4; ++e) {
        const int n = n4 + e;
        const bool um = (mr != 0) && (mcs[e] != 0);
        if (um && m <= n) {
            const float qk = qrow[rks[e]];
            (&v0.x)[e] = fmaf(qk, 0.03125f, (&be0.x)[e]) + bo0;
            (&v1.x)[e] = fmaf(qk, 0.03125f, (&be1.x)[e]) + bo1;
        } else {
            const float f = (m > n && !um) ? -2e12f : -1e12f;
            (&v0.x)[e] = f;
            (&v1.x)[e] = f;
        }
    }
    *(float4*)(o0 + n4) = v0;
    *(float4*)(o1 + n4) = v1;
}

// -------------------- prep: fused hidden->fp16 convert + bias GEMV ----------
__global__ __launch_bounds__(256) void prep_hidden(const float* __restrict__ hidden,
                                                   const float* __restrict__ W2,
                                                   const float* __restrict__ b2)
{
    const int wid = threadIdx.x >> 5, lane = threadIdx.x & 31;
    const int row = blockIdx.x * 8 + wid;                     // 0..16383
    const float* h = hidden + (size_t)row * 1024;
    __half* o = g_hbf + (size_t)row * 1024;
    float a0 = 0.f, a1 = 0.f, a2 = 0.f, a3 = 0.f;
    #pragma unroll
    for (int i = 0; i < 8; ++i) {
        const int c4 = i * 32 + lane;
        float4 v = *(const float4*)&h[c4 * 4];
        __half2 h0 = __floats2half2_rn(v.x, v.y);
        __half2 h1 = __floats2half2_rn(v.z, v.w);
        uint2 st;
        st.x = *reinterpret_cast<uint32_t*>(&h0);
        st.y = *reinterpret_cast<uint32_t*>(&h1);
        *(uint2*)&o[c4 * 4] = st;
        const int k = c4 * 4;
        float4 w0 = *(const float4*)&W2[(k + 0) * 4];
        float4 w1 = *(const float4*)&W2[(k + 1) * 4];
        float4 w2 = *(const float4*)&W2[(k + 2) * 4];
        float4 w3 = *(const float4*)&W2[(k + 3) * 4];
        a0 += v.x * w0.x + v.y * w1.x + v.z * w2.x + v.w * w3.x;
        a1 += v.x * w0.y + v.y * w1.y + v.z * w2.y + v.w * w3.y;
        a2 += v.x * w0.z + v.y * w1.z + v.z * w2.z + v.w * w3.z;
        a3 += v.x * w0.w + v.y * w1.w + v.z * w2.w + v.w * w3.w;
    }
    #pragma unroll
    for (int off = 16; off > 0; off >>= 1) {
        a0 += __shfl_xor_sync(0xFFFFFFFF, a0, off);
        a1 += __shfl_xor_sync(0xFFFFFFFF, a1, off);
        a2 += __shfl_xor_sync(0xFFFFFFFF, a2, off);
        a3 += __shfl_xor_sync(0xFFFFFFFF, a3, off);
    }
    if (lane == 0) {
        const int bb = row >> 10, l = row & 1023;
        float* bp = g_bias + (size_t)bb * 4096 + l;
        bp[0]    = (a0 + b2[0]) * 0.5f;
        bp[1024] = (a1 + b2[1]) * 0.5f;
        bp[2048] = (a2 + b2[2]) * 0.5f;
        bp[3072] = (a3 + b2[3]) * 0.5f;
    }
}

__global__ __launch_bounds__(256) void transpose_w1(const float* __restrict__ W1)
{
    __shared__ float tile[32][33];
    const int tx = threadIdx.x & 31, ty = threadIdx.x >> 5;   // 32x8
    const int nb = blockIdx.x * 32, kb = blockIdx.y * 32;
    #pragma unroll
    for (int i = 0; i < 4; ++i)
        tile[ty + i * 8][tx] = W1[(size_t)(kb + ty + i * 8) * 2048 + nb + tx];
    __syncthreads();
    #pragma unroll
    for (int i = 0; i < 4; ++i)
        g_w1t[(size_t)(nb + ty + i * 8) * 1024 + kb + tx] = __float2half_rn(tile[tx][ty + i * 8]);
}

// -------------------- launch --------------------
extern "C" void kernel_launch(void* const* d_in, const int* in_sizes, int n_in,
                              void* d_out, int out_size)
{
    const float* hidden = (const float*)d_in[0];
    const int*   tt     = (const int*)d_in[1];
    const float* W1     = (const float*)d_in[2];
    const float* b1     = (const float*)d_in[3];
    const float* W2     = (const float*)d_in[4];
    const float* b2     = (const float*)d_in[5];
    float* out = (float*)d_out;

    cudaFuncSetAttribute(gemm1_kernel, cudaFuncAttributeMaxDynamicSharedMemorySize, DYN_SMEM);
    cudaFuncSetAttribute(gemm2_kernel, cudaFuncAttributeMaxDynamicSharedMemorySize, DYN_SMEM);

    compact_kernel<<<BATCH, 1024>>>(tt);
    prep_hidden<<<2048, 256>>>(hidden, W2, b2);
    transpose_w1<<<dim3(64, 32), dim3(256)>>>(W1);

    dim3 g1(16, 8, BATCH);            // N/128 x Mc-tiles x B (early-exit on cnt)
    gemm1_kernel<<<g1, 256, DYN_SMEM>>>(b1);

    dim3 g2(8, 8, BATCH);             // Nc x Mc x B (early-exit on cnt/triangle)
    gemm2_kernel<<<g2, 256, DYN_SMEM>>>();

    dim3 gs(LSEQ, BATCH);             // one block per output row
    scatter_kernel<<<gs, 256>>>(tt, out);
}